// round 7
// baseline (speedup 1.0000x reference)
#include <cuda_runtime.h>
#include <cuda_bf16.h>
#include <math.h>

#define NN 50000
#define NE 800000
#define E2 (NE + NN)          // 850000 edges incl. self loops
#define HC 128
#define H 4
#define NEG 0.2f
#define BN_EPS 1e-5f

// ---------------- scratch (__device__ globals; no allocation allowed) ----------
__device__ float g_xl[NN * HC];   // HEAD-INTERLEAVED: [node][lane(32)][head(4)]
__device__ float g_xr[NN * HC];   // standard [node][h*32+lane]
__device__ float g_h1[NN * HC];   // standard
__device__ int   g_deg[NN];
__device__ float g_wsum[NN];
__device__ float g_loop[NN];
__device__ int   g_rowptr[NN + 1];
__device__ int   g_fill[NN];
__device__ int   g_bsum[32];
__device__ int   g_boff[32];
__device__ int   g_csrc[E2];
__device__ float g_cw[E2];
__device__ float g_chsum[HC];
__device__ float g_chsq[HC];

// ---------------- init ---------------------------------------------------------
__global__ void zero_kernel() {
    int i = blockIdx.x * blockDim.x + threadIdx.x;
    if (i < NN) { g_deg[i] = 0; g_wsum[i] = 0.f; g_fill[i] = 0; }
    if (i < HC) { g_chsum[i] = 0.f; g_chsq[i] = 0.f; }
}

// ---------------- degree + weight sum per dst ----------------------------------
__global__ void deg_kernel(const int* __restrict__ ei, const float* __restrict__ ew) {
    int e = blockIdx.x * blockDim.x + threadIdx.x;
    if (e >= NE) return;
    int d = ei[NE + e];
    atomicAdd(&g_deg[d], 1);
    atomicAdd(&g_wsum[d], ew[e]);
}

// ---------------- 3-phase exclusive scan of (deg[v]+1) -------------------------
__global__ void scan_blocksum() {
    __shared__ int sd[256];
    int t = threadIdx.x;
    int base = blockIdx.x * 2048 + t * 8;
    int s = 0;
#pragma unroll
    for (int j = 0; j < 8; j++) { int v = base + j; if (v < NN) s += g_deg[v] + 1; }
    sd[t] = s; __syncthreads();
    for (int off = 128; off > 0; off >>= 1) {
        if (t < off) sd[t] += sd[t + off];
        __syncthreads();
    }
    if (t == 0) g_bsum[blockIdx.x] = sd[0];
}

__global__ void scan_boff(int nblk) {
    if (threadIdx.x == 0 && blockIdx.x == 0) {
        int r = 0;
        for (int b = 0; b < nblk; b++) { g_boff[b] = r; r += g_bsum[b]; }
        g_rowptr[NN] = r;   // == E2
    }
}

__global__ void scan_write() {      // also computes self-loop attr (folded)
    __shared__ int sd[256];
    int t = threadIdx.x;
    int base = blockIdx.x * 2048 + t * 8;
    int cnt[8];
    int s = 0;
#pragma unroll
    for (int j = 0; j < 8; j++) {
        int v = base + j;
        cnt[j] = (v < NN) ? (g_deg[v] + 1) : 0;
        s += cnt[j];
    }
    sd[t] = s; __syncthreads();
    for (int off = 1; off < 256; off <<= 1) {
        int val = (t >= off) ? sd[t - off] : 0;
        __syncthreads();
        sd[t] += val;
        __syncthreads();
    }
    int excl = sd[t] - s + g_boff[blockIdx.x];
#pragma unroll
    for (int j = 0; j < 8; j++) {
        int v = base + j;
        if (v < NN) {
            g_rowptr[v] = excl;
            g_loop[v] = g_wsum[v] / fmaxf((float)(cnt[j] - 1), 1.f);
        }
        excl += cnt[j];
    }
}

// ---------------- scatter edges into CSR by dst --------------------------------
__global__ void scatter_kernel(const int* __restrict__ ei, const float* __restrict__ ew) {
    int e = blockIdx.x * blockDim.x + threadIdx.x;
    if (e >= E2) return;
    int s, d; float w;
    if (e < NE) {
        s = ei[e];
        d = ei[NE + e];
        w = ew[e];
    } else {
        s = d = e - NE;
        w = g_loop[e - NE];
    }
    int pos = g_rowptr[d] + atomicAdd(&g_fill[d], 1);
    g_csrc[pos] = s;
    g_cw[pos] = w;
}

// ---------------- tf32 tensor-core dual GEMM -----------------------------------
// g_xl = x@Wl+bl (head-interleaved layout) ; g_xr = x@Wr+br (standard).
// FROM_H1: input is g_h1 with fused BatchNorm+ELU applied on load (and written
// back to g_h1 for the final residual).
#define LDW 136
#define LDX 132
#define GEMM_SMEM_BYTES ((2 * 128 * LDW + 64 * LDX + 256) * 4)

__device__ __forceinline__ unsigned f2tf(float f) {
    unsigned r; asm("cvt.rna.tf32.f32 %0, %1;" : "=r"(r) : "f"(f)); return r;
}

__device__ __forceinline__ void mma8(float c[4],
                                     unsigned a0, unsigned a1, unsigned a2, unsigned a3,
                                     unsigned b0, unsigned b1) {
    asm volatile("mma.sync.aligned.m16n8k8.row.col.f32.tf32.tf32.f32 "
                 "{%0,%1,%2,%3},{%4,%5,%6,%7},{%8,%9},{%0,%1,%2,%3};"
                 : "+f"(c[0]), "+f"(c[1]), "+f"(c[2]), "+f"(c[3])
                 : "r"(a0), "r"(a1), "r"(a2), "r"(a3), "r"(b0), "r"(b1));
}

template <bool FROM_H1>
__global__ void gemm2_kernel(const float* __restrict__ x_ext,
                             const float* __restrict__ Wl, const float* __restrict__ bl,
                             const float* __restrict__ Wr, const float* __restrict__ br,
                             const float* __restrict__ gamma, const float* __restrict__ beta) {
    const float* __restrict__ x = FROM_H1 ? (const float*)g_h1 : x_ext;
    extern __shared__ unsigned sm[];
    unsigned* sWl = sm;
    unsigned* sWr = sm + 128 * LDW;
    unsigned* sx  = sm + 2 * 128 * LDW;
    float*    sbn = (float*)(sm + 2 * 128 * LDW + 64 * LDX);   // [scale 128][shift 128]
    int tid = threadIdx.x;
    int lane = tid & 31, w = tid >> 5;
    int rg = w & 3, cg = w >> 2;

    if (FROM_H1 && tid < 128) {
        float mu = g_chsum[tid] * (1.f / NN);
        float var = g_chsq[tid] * (1.f / NN) - mu * mu;
        float inv = rsqrtf(fmaxf(var, 0.f) + BN_EPS);
        float sc = gamma[tid] * inv;
        sbn[tid] = sc;
        sbn[128 + tid] = beta[tid] - mu * sc;
    }

    // load W once per block, tf32-converted, layout sW[k][n]
    for (int i = tid; i < 128 * 128; i += 256) {
        int k = i >> 7, n = i & 127;
        sWl[k * LDW + n] = f2tf(Wl[i]);
        sWr[k * LDW + n] = f2tf(Wr[i]);
    }

    int ntiles = (NN + 63) / 64;
    for (int tile = blockIdx.x; tile < ntiles; tile += gridDim.x) {
        int t0 = tile * 64;
        __syncthreads();
        for (int i = tid; i < 64 * 128; i += 256) {
            int r = i >> 7, c = i & 127;
            int row = t0 + r;
            float xv = (row < NN) ? x[row * 128 + c] : 0.f;
            if (FROM_H1 && row < NN) {
                float y = sbn[c] * xv + sbn[128 + c];
                y = (y > 0.f) ? y : (__expf(y) - 1.f);
                g_h1[row * 128 + c] = y;     // post-BN value for final residual
                xv = y;
            }
            sx[r * LDX + c] = f2tf(xv);
        }
        __syncthreads();

        float cl[8][4], cr[8][4];
#pragma unroll
        for (int t = 0; t < 8; t++)
#pragma unroll
            for (int j = 0; j < 4; j++) { cl[t][j] = 0.f; cr[t][j] = 0.f; }

        int arow = rg * 16 + (lane >> 2);
        int bcol0 = cg * 64 + (lane >> 2);
#pragma unroll 4
        for (int ks = 0; ks < 16; ks++) {
            int k0 = ks * 8;
            int acol = k0 + (lane & 3);
            unsigned a0 = sx[arow * LDX + acol];
            unsigned a1 = sx[(arow + 8) * LDX + acol];
            unsigned a2 = sx[arow * LDX + acol + 4];
            unsigned a3 = sx[(arow + 8) * LDX + acol + 4];
            int brow = k0 + (lane & 3);
#pragma unroll
            for (int t = 0; t < 8; t++) {
                int n = bcol0 + t * 8;
                unsigned b0 = sWl[brow * LDW + n];
                unsigned b1 = sWl[(brow + 4) * LDW + n];
                mma8(cl[t], a0, a1, a2, a3, b0, b1);
                unsigned d0 = sWr[brow * LDW + n];
                unsigned d1 = sWr[(brow + 4) * LDW + n];
                mma8(cr[t], a0, a1, a2, a3, d0, d1);
            }
        }

        int orow = t0 + rg * 16 + (lane >> 2);
#pragma unroll
        for (int t = 0; t < 8; t++) {
            int n = cg * 64 + t * 8 + 2 * (lane & 3);
            int l = n & 31, h = n >> 5;       // n and n+1 share h (n&31 <= 30)
            float bl0 = bl[n], bl1 = bl[n + 1];
            float br0 = br[n], br1 = br[n + 1];
            if (orow < NN) {
                g_xl[orow * 128 + l * 4 + h]       = cl[t][0] + bl0;
                g_xl[orow * 128 + (l + 1) * 4 + h] = cl[t][1] + bl1;
                float2 u; u.x = cr[t][0] + br0; u.y = cr[t][1] + br1;
                *(float2*)&g_xr[orow * 128 + n] = u;
            }
            if (orow + 8 < NN) {
                g_xl[(orow + 8) * 128 + l * 4 + h]       = cl[t][2] + bl0;
                g_xl[(orow + 8) * 128 + (l + 1) * 4 + h] = cl[t][3] + bl1;
                float2 u; u.x = cr[t][2] + br0; u.y = cr[t][3] + br1;
                *(float2*)&g_xr[(orow + 8) * 128 + n] = u;
            }
        }
    }
}

// ---------------- warp-per-node GATv2 edge phase (max-free softmax) ------------
// g_xl head-interleaved: one float4 gather per edge per lane. 2x unrolled for
// ILP across the shfl-reduction chains.
__device__ __forceinline__ float packed_reduce(const float p[4], int lane) {
    float a02 = (lane & 16) ? p[0] : p[2];
    float b02 = __shfl_xor_sync(0xffffffffu, a02, 16);
    float r02 = ((lane & 16) ? p[2] : p[0]) + b02;
    float a13 = (lane & 16) ? p[1] : p[3];
    float b13 = __shfl_xor_sync(0xffffffffu, a13, 16);
    float r13 = ((lane & 16) ? p[3] : p[1]) + b13;
    float a = (lane & 8) ? r02 : r13;
    float b = __shfl_xor_sync(0xffffffffu, a, 8);
    float r = ((lane & 8) ? r13 : r02) + b;
    r += __shfl_xor_sync(0xffffffffu, r, 4);
    r += __shfl_xor_sync(0xffffffffu, r, 2);
    r += __shfl_xor_sync(0xffffffffu, r, 1);
    return r;   // lane group g=lane/8 holds head-g logit
}

template <bool FINAL>
__global__ void gat_edge_kernel(const float* __restrict__ We, const float* __restrict__ att,
                                const float* __restrict__ bias,
                                const float* __restrict__ emb,
                                float* __restrict__ out_ext) {
    int gw = (blockIdx.x * blockDim.x + threadIdx.x) >> 5;
    if (gw >= NN) return;
    int lane = threadIdx.x & 31;
    int v = gw;
    const float4* __restrict__ xl4 = (const float4*)g_xl;

    float we[H], at[H], xrv[H];
#pragma unroll
    for (int h = 0; h < H; h++) {
        we[h]  = We[h * 32 + lane];
        at[h]  = att[h * 32 + lane];
        xrv[h] = g_xr[v * 128 + h * 32 + lane];
    }
    float s[H] = {0.f, 0.f, 0.f, 0.f};
    float acc[H] = {0.f, 0.f, 0.f, 0.f};

    int beg = g_rowptr[v], end = g_rowptr[v + 1];
    int i = beg;
    for (; i + 2 <= end; i += 2) {
        int s0 = g_csrc[i], s1 = g_csrc[i + 1];
        float w0 = g_cw[i], w1 = g_cw[i + 1];
        float4 xA = xl4[(size_t)s0 * 32 + lane];
        float4 xB = xl4[(size_t)s1 * 32 + lane];
        float xa[4] = {xA.x, xA.y, xA.z, xA.w};
        float xb[4] = {xB.x, xB.y, xB.z, xB.w};
        float pA[4], pB[4];
#pragma unroll
        for (int h = 0; h < H; h++) {
            float tA = xa[h] + xrv[h] + w0 * we[h];
            tA = (tA > 0.f) ? tA : NEG * tA;
            pA[h] = tA * at[h];
            float tB = xb[h] + xrv[h] + w1 * we[h];
            tB = (tB > 0.f) ? tB : NEG * tB;
            pB[h] = tB * at[h];
        }
        float rA = packed_reduce(pA, lane);
        float rB = packed_reduce(pB, lane);
        float eA = __expf(rA), eB = __expf(rB);
        float eA0 = __shfl_sync(0xffffffffu, eA, 0);
        float eA1 = __shfl_sync(0xffffffffu, eA, 8);
        float eA2 = __shfl_sync(0xffffffffu, eA, 16);
        float eA3 = __shfl_sync(0xffffffffu, eA, 24);
        float eB0 = __shfl_sync(0xffffffffu, eB, 0);
        float eB1 = __shfl_sync(0xffffffffu, eB, 8);
        float eB2 = __shfl_sync(0xffffffffu, eB, 16);
        float eB3 = __shfl_sync(0xffffffffu, eB, 24);
        s[0] += eA0 + eB0; acc[0] += xa[0] * eA0 + xb[0] * eB0;
        s[1] += eA1 + eB1; acc[1] += xa[1] * eA1 + xb[1] * eB1;
        s[2] += eA2 + eB2; acc[2] += xa[2] * eA2 + xb[2] * eB2;
        s[3] += eA3 + eB3; acc[3] += xa[3] * eA3 + xb[3] * eB3;
    }
    if (i < end) {
        int s0 = g_csrc[i];
        float w0 = g_cw[i];
        float4 xA = xl4[(size_t)s0 * 32 + lane];
        float xa[4] = {xA.x, xA.y, xA.z, xA.w};
        float pA[4];
#pragma unroll
        for (int h = 0; h < H; h++) {
            float tA = xa[h] + xrv[h] + w0 * we[h];
            tA = (tA > 0.f) ? tA : NEG * tA;
            pA[h] = tA * at[h];
        }
        float rA = packed_reduce(pA, lane);
        float eA = __expf(rA);
        float eA0 = __shfl_sync(0xffffffffu, eA, 0);
        float eA1 = __shfl_sync(0xffffffffu, eA, 8);
        float eA2 = __shfl_sync(0xffffffffu, eA, 16);
        float eA3 = __shfl_sync(0xffffffffu, eA, 24);
        s[0] += eA0; acc[0] += xa[0] * eA0;
        s[1] += eA1; acc[1] += xa[1] * eA1;
        s[2] += eA2; acc[2] += xa[2] * eA2;
        s[3] += eA3; acc[3] += xa[3] * eA3;
    }
#pragma unroll
    for (int h = 0; h < H; h++) {
        float o = acc[h] / s[h] + bias[h * 32 + lane];
        int idx = v * 128 + h * 32 + lane;
        if (FINAL) {
            o = (emb[idx] + g_h1[idx] + o) * (1.f / 3.f);
            out_ext[idx] = o;
        } else {
            g_h1[idx] = o;
        }
    }
}

// ---------------- batch norm stats (on g_h1) ------------------------------------
__global__ void bn_stats_kernel() {
    int c = threadIdx.x;  // 128 threads
    float s = 0.f, q = 0.f;
    for (int v = blockIdx.x; v < NN; v += gridDim.x) {
        float x = g_h1[v * 128 + c];
        s += x; q += x * x;
    }
    atomicAdd(&g_chsum[c], s);
    atomicAdd(&g_chsq[c], q);
}

// ---------------- launch --------------------------------------------------------
extern "C" void kernel_launch(void* const* d_in, const int* in_sizes, int n_in,
                              void* d_out, int out_size) {
    const float* emb   = (const float*)d_in[0];
    const int*   ei    = (const int*)d_in[1];
    const float* ew    = (const float*)d_in[2];
    const float* Wl1 = (const float*)d_in[3];
    const float* bl1 = (const float*)d_in[4];
    const float* Wr1 = (const float*)d_in[5];
    const float* br1 = (const float*)d_in[6];
    const float* We1 = (const float*)d_in[7];
    const float* att1 = (const float*)d_in[8];
    const float* bias1 = (const float*)d_in[9];
    const float* gamma1 = (const float*)d_in[10];
    const float* beta1 = (const float*)d_in[11];
    const float* Wl2 = (const float*)d_in[12];
    const float* bl2 = (const float*)d_in[13];
    const float* Wr2 = (const float*)d_in[14];
    const float* br2 = (const float*)d_in[15];
    const float* We2 = (const float*)d_in[16];
    const float* att2 = (const float*)d_in[17];
    const float* bias2 = (const float*)d_in[18];
    float* out = (float*)d_out;

    cudaFuncSetAttribute(gemm2_kernel<false>,
                         cudaFuncAttributeMaxDynamicSharedMemorySize, GEMM_SMEM_BYTES);
    cudaFuncSetAttribute(gemm2_kernel<true>,
                         cudaFuncAttributeMaxDynamicSharedMemorySize, GEMM_SMEM_BYTES);

    // graph build (self loops + CSR by dst)
    zero_kernel<<<(NN + 255) / 256, 256>>>();
    deg_kernel<<<(NE + 255) / 256, 256>>>(ei, ew);
    scan_blocksum<<<25, 256>>>();
    scan_boff<<<1, 32>>>(25);
    scan_write<<<25, 256>>>();
    scatter_kernel<<<(E2 + 255) / 256, 256>>>(ei, ew);

    // layer 1
    gemm2_kernel<false><<<148, 256, GEMM_SMEM_BYTES>>>(emb, Wl1, bl1, Wr1, br1,
                                                       nullptr, nullptr);
    gat_edge_kernel<false><<<(NN * 32 + 255) / 256, 256>>>(We1, att1, bias1, nullptr, nullptr);
    bn_stats_kernel<<<296, 128>>>();

    // layer 2 (BN+ELU fused into GEMM load; final mean fused into edge kernel)
    gemm2_kernel<true><<<148, 256, GEMM_SMEM_BYTES>>>(nullptr, Wl2, bl2, Wr2, br2,
                                                      gamma1, beta1);
    gat_edge_kernel<true><<<(NN * 32 + 255) / 256, 256>>>(We2, att2, bias2, emb, out);
}

// round 8
// speedup vs baseline: 1.0381x; 1.0381x over previous
#include <cuda_runtime.h>
#include <cuda_bf16.h>
#include <math.h>

#define NN 50000
#define NE 800000
#define E2 (NE + NN)          // 850000 edges incl. self loops
#define HC 128
#define H 4
#define NEG 0.2f
#define BN_EPS 1e-5f

// ---------------- scratch (__device__ globals; no allocation allowed) ----------
__device__ float g_xl[NN * HC];   // HEAD-INTERLEAVED: [node][lane(32)][head(4)]
__device__ float g_xr[NN * HC];   // standard [node][h*32+lane]
__device__ float g_h1[NN * HC];   // standard
__device__ int   g_deg[NN];
__device__ float g_wsum[NN];
__device__ float g_loop[NN];
__device__ int   g_rowptr[NN + 1];
__device__ int   g_fill[NN];
__device__ int   g_bsum[32];
__device__ int   g_boff[32];
__device__ int   g_csrc[E2];
__device__ float g_cw[E2];
__device__ float g_chsum[HC];
__device__ float g_chsq[HC];

// ---------------- init ---------------------------------------------------------
__global__ void zero_kernel() {
    int i = blockIdx.x * blockDim.x + threadIdx.x;
    if (i < NN) { g_deg[i] = 0; g_wsum[i] = 0.f; g_fill[i] = 0; }
    if (i < HC) { g_chsum[i] = 0.f; g_chsq[i] = 0.f; }
}

// ---------------- degree + weight sum per dst ----------------------------------
__global__ void deg_kernel(const int* __restrict__ ei, const float* __restrict__ ew) {
    int e = blockIdx.x * blockDim.x + threadIdx.x;
    if (e >= NE) return;
    int d = ei[NE + e];
    atomicAdd(&g_deg[d], 1);
    atomicAdd(&g_wsum[d], ew[e]);
}

// ---------------- 3-phase exclusive scan of (deg[v]+1) -------------------------
__global__ void scan_blocksum() {
    __shared__ int sd[256];
    int t = threadIdx.x;
    int base = blockIdx.x * 2048 + t * 8;
    int s = 0;
#pragma unroll
    for (int j = 0; j < 8; j++) { int v = base + j; if (v < NN) s += g_deg[v] + 1; }
    sd[t] = s; __syncthreads();
    for (int off = 128; off > 0; off >>= 1) {
        if (t < off) sd[t] += sd[t + off];
        __syncthreads();
    }
    if (t == 0) g_bsum[blockIdx.x] = sd[0];
}

__global__ void scan_boff(int nblk) {
    if (threadIdx.x == 0 && blockIdx.x == 0) {
        int r = 0;
        for (int b = 0; b < nblk; b++) { g_boff[b] = r; r += g_bsum[b]; }
        g_rowptr[NN] = r;   // == E2
    }
}

__global__ void scan_write() {      // also computes self-loop attr (folded)
    __shared__ int sd[256];
    int t = threadIdx.x;
    int base = blockIdx.x * 2048 + t * 8;
    int cnt[8];
    int s = 0;
#pragma unroll
    for (int j = 0; j < 8; j++) {
        int v = base + j;
        cnt[j] = (v < NN) ? (g_deg[v] + 1) : 0;
        s += cnt[j];
    }
    sd[t] = s; __syncthreads();
    for (int off = 1; off < 256; off <<= 1) {
        int val = (t >= off) ? sd[t - off] : 0;
        __syncthreads();
        sd[t] += val;
        __syncthreads();
    }
    int excl = sd[t] - s + g_boff[blockIdx.x];
#pragma unroll
    for (int j = 0; j < 8; j++) {
        int v = base + j;
        if (v < NN) {
            g_rowptr[v] = excl;
            g_loop[v] = g_wsum[v] / fmaxf((float)(cnt[j] - 1), 1.f);
        }
        excl += cnt[j];
    }
}

// ---------------- scatter edges into CSR by dst --------------------------------
__global__ void scatter_kernel(const int* __restrict__ ei, const float* __restrict__ ew) {
    int e = blockIdx.x * blockDim.x + threadIdx.x;
    if (e >= E2) return;
    int s, d; float w;
    if (e < NE) {
        s = ei[e];
        d = ei[NE + e];
        w = ew[e];
    } else {
        s = d = e - NE;
        w = g_loop[e - NE];
    }
    int pos = g_rowptr[d] + atomicAdd(&g_fill[d], 1);
    g_csrc[pos] = s;
    g_cw[pos] = w;
}

// ---------------- tf32 tensor-core dual GEMM -----------------------------------
// g_xl = x@Wl+bl (head-interleaved, staged via smem -> coalesced STG.128);
// g_xr = x@Wr+br (standard). FROM_H1: fused BatchNorm+ELU on load, written back
// to g_h1 for the final residual.
#define LDW 136
#define LDX 132
#define GEMM_SMEM_BYTES ((2 * 128 * LDW + 64 * LDX + 256) * 4)

__device__ __forceinline__ unsigned f2tf(float f) {
    unsigned r; asm("cvt.rna.tf32.f32 %0, %1;" : "=r"(r) : "f"(f)); return r;
}

__device__ __forceinline__ void mma8(float c[4],
                                     unsigned a0, unsigned a1, unsigned a2, unsigned a3,
                                     unsigned b0, unsigned b1) {
    asm volatile("mma.sync.aligned.m16n8k8.row.col.f32.tf32.tf32.f32 "
                 "{%0,%1,%2,%3},{%4,%5,%6,%7},{%8,%9},{%0,%1,%2,%3};"
                 : "+f"(c[0]), "+f"(c[1]), "+f"(c[2]), "+f"(c[3])
                 : "r"(a0), "r"(a1), "r"(a2), "r"(a3), "r"(b0), "r"(b1));
}

template <bool FROM_H1>
__global__ void gemm2_kernel(const float* __restrict__ x_ext,
                             const float* __restrict__ Wl, const float* __restrict__ bl,
                             const float* __restrict__ Wr, const float* __restrict__ br,
                             const float* __restrict__ gamma, const float* __restrict__ beta) {
    const float* __restrict__ x = FROM_H1 ? (const float*)g_h1 : x_ext;
    extern __shared__ unsigned sm[];
    unsigned* sWl = sm;
    unsigned* sWr = sm + 128 * LDW;
    unsigned* sx  = sm + 2 * 128 * LDW;
    float*    sout = (float*)sx;                                // reused post-MMA
    float*    sbn = (float*)(sm + 2 * 128 * LDW + 64 * LDX);    // [scale 128][shift 128]
    int tid = threadIdx.x;
    int lane = tid & 31, w = tid >> 5;
    int rg = w & 3, cg = w >> 2;

    if (FROM_H1 && tid < 128) {
        float mu = g_chsum[tid] * (1.f / NN);
        float var = g_chsq[tid] * (1.f / NN) - mu * mu;
        float inv = rsqrtf(fmaxf(var, 0.f) + BN_EPS);
        float sc = gamma[tid] * inv;
        sbn[tid] = sc;
        sbn[128 + tid] = beta[tid] - mu * sc;
    }

    // load W once per block, tf32-converted, layout sW[k][n]
    for (int i = tid; i < 128 * 128; i += 256) {
        int k = i >> 7, n = i & 127;
        sWl[k * LDW + n] = f2tf(Wl[i]);
        sWr[k * LDW + n] = f2tf(Wr[i]);
    }

    int ntiles = (NN + 63) / 64;
    for (int tile = blockIdx.x; tile < ntiles; tile += gridDim.x) {
        int t0 = tile * 64;
        __syncthreads();
        for (int i = tid; i < 64 * 128; i += 256) {
            int r = i >> 7, c = i & 127;
            int row = t0 + r;
            float xv = (row < NN) ? x[row * 128 + c] : 0.f;
            if (FROM_H1 && row < NN) {
                float y = sbn[c] * xv + sbn[128 + c];
                y = (y > 0.f) ? y : (__expf(y) - 1.f);
                g_h1[row * 128 + c] = y;     // post-BN value for final residual
                xv = y;
            }
            sx[r * LDX + c] = f2tf(xv);
        }
        __syncthreads();

        float cl[8][4], cr[8][4];
#pragma unroll
        for (int t = 0; t < 8; t++)
#pragma unroll
            for (int j = 0; j < 4; j++) { cl[t][j] = 0.f; cr[t][j] = 0.f; }

        int arow = rg * 16 + (lane >> 2);
        int bcol0 = cg * 64 + (lane >> 2);
#pragma unroll 4
        for (int ks = 0; ks < 16; ks++) {
            int k0 = ks * 8;
            int acol = k0 + (lane & 3);
            unsigned a0 = sx[arow * LDX + acol];
            unsigned a1 = sx[(arow + 8) * LDX + acol];
            unsigned a2 = sx[arow * LDX + acol + 4];
            unsigned a3 = sx[(arow + 8) * LDX + acol + 4];
            int brow = k0 + (lane & 3);
#pragma unroll
            for (int t = 0; t < 8; t++) {
                int n = bcol0 + t * 8;
                unsigned b0 = sWl[brow * LDW + n];
                unsigned b1 = sWl[(brow + 4) * LDW + n];
                mma8(cl[t], a0, a1, a2, a3, b0, b1);
                unsigned d0 = sWr[brow * LDW + n];
                unsigned d1 = sWr[(brow + 4) * LDW + n];
                mma8(cr[t], a0, a1, a2, a3, d0, d1);
            }
        }

        // g_xr: direct coalesced float2 stores (register path, no smem needed)
        int orow = t0 + rg * 16 + (lane >> 2);
#pragma unroll
        for (int t = 0; t < 8; t++) {
            int n = cg * 64 + t * 8 + 2 * (lane & 3);
            float br0 = br[n], br1 = br[n + 1];
            if (orow < NN) {
                float2 u; u.x = cr[t][0] + br0; u.y = cr[t][1] + br1;
                *(float2*)&g_xr[orow * 128 + n] = u;
            }
            if (orow + 8 < NN) {
                float2 u; u.x = cr[t][2] + br0; u.y = cr[t][3] + br1;
                *(float2*)&g_xr[(orow + 8) * 128 + n] = u;
            }
        }

        // g_xl: stage interleaved layout in smem (sx is dead now), then write
        // fully-coalesced float4 rows.
        __syncthreads();   // all MMA reads of sx complete
        {
            int r0 = rg * 16 + (lane >> 2);
#pragma unroll
            for (int t = 0; t < 8; t++) {
                int n = cg * 64 + t * 8 + 2 * (lane & 3);
                int hh = n >> 5;
                int ic0 = (n & 31) * 4 + hh;
                int ic1 = ((n + 1) & 31) * 4 + hh;
                float b0 = bl[n], b1 = bl[n + 1];
                sout[r0 * LDX + ic0] = cl[t][0] + b0;
                sout[r0 * LDX + ic1] = cl[t][1] + b1;
                sout[(r0 + 8) * LDX + ic0] = cl[t][2] + b0;
                sout[(r0 + 8) * LDX + ic1] = cl[t][3] + b1;
            }
        }
        __syncthreads();
        for (int i2 = tid; i2 < 64 * 32; i2 += 256) {
            int r = i2 >> 5, c4 = i2 & 31;
            int row = t0 + r;
            if (row < NN) {
                float4 vv = *(float4*)&sout[r * LDX + c4 * 4];
                *(float4*)&g_xl[row * 128 + c4 * 4] = vv;
            }
        }
    }
}

// ---------------- warp-per-node GATv2 edge phase (max-free softmax) ------------
__device__ __forceinline__ float packed_reduce(const float p[4], int lane) {
    float a02 = (lane & 16) ? p[0] : p[2];
    float b02 = __shfl_xor_sync(0xffffffffu, a02, 16);
    float r02 = ((lane & 16) ? p[2] : p[0]) + b02;
    float a13 = (lane & 16) ? p[1] : p[3];
    float b13 = __shfl_xor_sync(0xffffffffu, a13, 16);
    float r13 = ((lane & 16) ? p[3] : p[1]) + b13;
    float a = (lane & 8) ? r02 : r13;
    float b = __shfl_xor_sync(0xffffffffu, a, 8);
    float r = ((lane & 8) ? r13 : r02) + b;
    r += __shfl_xor_sync(0xffffffffu, r, 4);
    r += __shfl_xor_sync(0xffffffffu, r, 2);
    r += __shfl_xor_sync(0xffffffffu, r, 1);
    return r;   // lane group g=lane/8 holds head-g logit
}

template <bool FINAL>
__global__ void gat_edge_kernel(const float* __restrict__ We, const float* __restrict__ att,
                                const float* __restrict__ bias,
                                const float* __restrict__ emb,
                                float* __restrict__ out_ext) {
    int gw = (blockIdx.x * blockDim.x + threadIdx.x) >> 5;
    if (gw >= NN) return;
    int lane = threadIdx.x & 31;
    int v = gw;
    const float4* __restrict__ xl4 = (const float4*)g_xl;

    float we[H], at[H], xrv[H];
#pragma unroll
    for (int h = 0; h < H; h++) {
        we[h]  = We[h * 32 + lane];
        at[h]  = att[h * 32 + lane];
        xrv[h] = g_xr[v * 128 + h * 32 + lane];
    }
    float s[H] = {0.f, 0.f, 0.f, 0.f};
    float acc[H] = {0.f, 0.f, 0.f, 0.f};

    int beg = g_rowptr[v], end = g_rowptr[v + 1];
    int i = beg;
    for (; i + 2 <= end; i += 2) {
        int s0 = g_csrc[i], s1 = g_csrc[i + 1];
        float w0 = g_cw[i], w1 = g_cw[i + 1];
        float4 xA = xl4[(size_t)s0 * 32 + lane];
        float4 xB = xl4[(size_t)s1 * 32 + lane];
        float xa[4] = {xA.x, xA.y, xA.z, xA.w};
        float xb[4] = {xB.x, xB.y, xB.z, xB.w};
        float pA[4], pB[4];
#pragma unroll
        for (int h = 0; h < H; h++) {
            float tA = xa[h] + xrv[h] + w0 * we[h];
            tA = (tA > 0.f) ? tA : NEG * tA;
            pA[h] = tA * at[h];
            float tB = xb[h] + xrv[h] + w1 * we[h];
            tB = (tB > 0.f) ? tB : NEG * tB;
            pB[h] = tB * at[h];
        }
        float rA = packed_reduce(pA, lane);
        float rB = packed_reduce(pB, lane);
        float eA = __expf(rA), eB = __expf(rB);
        float eA0 = __shfl_sync(0xffffffffu, eA, 0);
        float eA1 = __shfl_sync(0xffffffffu, eA, 8);
        float eA2 = __shfl_sync(0xffffffffu, eA, 16);
        float eA3 = __shfl_sync(0xffffffffu, eA, 24);
        float eB0 = __shfl_sync(0xffffffffu, eB, 0);
        float eB1 = __shfl_sync(0xffffffffu, eB, 8);
        float eB2 = __shfl_sync(0xffffffffu, eB, 16);
        float eB3 = __shfl_sync(0xffffffffu, eB, 24);
        s[0] += eA0 + eB0; acc[0] += xa[0] * eA0 + xb[0] * eB0;
        s[1] += eA1 + eB1; acc[1] += xa[1] * eA1 + xb[1] * eB1;
        s[2] += eA2 + eB2; acc[2] += xa[2] * eA2 + xb[2] * eB2;
        s[3] += eA3 + eB3; acc[3] += xa[3] * eA3 + xb[3] * eB3;
    }
    if (i < end) {
        int s0 = g_csrc[i];
        float w0 = g_cw[i];
        float4 xA = xl4[(size_t)s0 * 32 + lane];
        float xa[4] = {xA.x, xA.y, xA.z, xA.w};
        float pA[4];
#pragma unroll
        for (int h = 0; h < H; h++) {
            float tA = xa[h] + xrv[h] + w0 * we[h];
            tA = (tA > 0.f) ? tA : NEG * tA;
            pA[h] = tA * at[h];
        }
        float rA = packed_reduce(pA, lane);
        float eA = __expf(rA);
        float eA0 = __shfl_sync(0xffffffffu, eA, 0);
        float eA1 = __shfl_sync(0xffffffffu, eA, 8);
        float eA2 = __shfl_sync(0xffffffffu, eA, 16);
        float eA3 = __shfl_sync(0xffffffffu, eA, 24);
        s[0] += eA0; acc[0] += xa[0] * eA0;
        s[1] += eA1; acc[1] += xa[1] * eA1;
        s[2] += eA2; acc[2] += xa[2] * eA2;
        s[3] += eA3; acc[3] += xa[3] * eA3;
    }
#pragma unroll
    for (int h = 0; h < H; h++) {
        float o = acc[h] / s[h] + bias[h * 32 + lane];
        int idx = v * 128 + h * 32 + lane;
        if (FINAL) {
            o = (emb[idx] + g_h1[idx] + o) * (1.f / 3.f);
            out_ext[idx] = o;
        } else {
            g_h1[idx] = o;
        }
    }
}

// ---------------- batch norm stats (on g_h1) ------------------------------------
__global__ void bn_stats_kernel() {
    int c = threadIdx.x;  // 128 threads
    float s = 0.f, q = 0.f;
    for (int v = blockIdx.x; v < NN; v += gridDim.x) {
        float x = g_h1[v * 128 + c];
        s += x; q += x * x;
    }
    atomicAdd(&g_chsum[c], s);
    atomicAdd(&g_chsq[c], q);
}

// ---------------- launch --------------------------------------------------------
extern "C" void kernel_launch(void* const* d_in, const int* in_sizes, int n_in,
                              void* d_out, int out_size) {
    const float* emb   = (const float*)d_in[0];
    const int*   ei    = (const int*)d_in[1];
    const float* ew    = (const float*)d_in[2];
    const float* Wl1 = (const float*)d_in[3];
    const float* bl1 = (const float*)d_in[4];
    const float* Wr1 = (const float*)d_in[5];
    const float* br1 = (const float*)d_in[6];
    const float* We1 = (const float*)d_in[7];
    const float* att1 = (const float*)d_in[8];
    const float* bias1 = (const float*)d_in[9];
    const float* gamma1 = (const float*)d_in[10];
    const float* beta1 = (const float*)d_in[11];
    const float* Wl2 = (const float*)d_in[12];
    const float* bl2 = (const float*)d_in[13];
    const float* Wr2 = (const float*)d_in[14];
    const float* br2 = (const float*)d_in[15];
    const float* We2 = (const float*)d_in[16];
    const float* att2 = (const float*)d_in[17];
    const float* bias2 = (const float*)d_in[18];
    float* out = (float*)d_out;

    cudaFuncSetAttribute(gemm2_kernel<false>,
                         cudaFuncAttributeMaxDynamicSharedMemorySize, GEMM_SMEM_BYTES);
    cudaFuncSetAttribute(gemm2_kernel<true>,
                         cudaFuncAttributeMaxDynamicSharedMemorySize, GEMM_SMEM_BYTES);

    // graph build (self loops + CSR by dst)
    zero_kernel<<<(NN + 255) / 256, 256>>>();
    deg_kernel<<<(NE + 255) / 256, 256>>>(ei, ew);
    scan_blocksum<<<25, 256>>>();
    scan_boff<<<1, 32>>>(25);
    scan_write<<<25, 256>>>();
    scatter_kernel<<<(E2 + 255) / 256, 256>>>(ei, ew);

    // layer 1
    gemm2_kernel<false><<<148, 256, GEMM_SMEM_BYTES>>>(emb, Wl1, bl1, Wr1, br1,
                                                       nullptr, nullptr);
    gat_edge_kernel<false><<<(NN * 32 + 255) / 256, 256>>>(We1, att1, bias1, nullptr, nullptr);
    bn_stats_kernel<<<296, 128>>>();

    // layer 2 (BN+ELU fused into GEMM load; final mean fused into edge kernel)
    gemm2_kernel<true><<<148, 256, GEMM_SMEM_BYTES>>>(nullptr, Wl2, bl2, Wr2, br2,
                                                      gamma1, beta1);
    gat_edge_kernel<true><<<(NN * 32 + 255) / 256, 256>>>(We2, att2, bias2, emb, out);
}